// round 5
// baseline (speedup 1.0000x reference)
#include <cuda_runtime.h>
#include <math.h>
#include <stdint.h>

#define N_PTS   16384
#define N_CODE  8192
#define E_DIM   256
#define Z_ELEMS 4194304            // 16*256*32*32
#define ONE_HOT_ELEMS 134217728LL  // 16384*8192

#define TM 64
#define TN 128
#define TK 32

// ---------------- device scratch (no allocations allowed) ----------------
__device__ int   g_indices[N_PTS];
__device__ int   g_counts[N_CODE];
__device__ float g_zsq[N_PTS];
__device__ float g_loss_part[N_PTS];

// ---------------- zero scratch ----------------
__global__ void vq_zero_kernel() {
    int i = blockIdx.x * blockDim.x + threadIdx.x;
    if (i < N_CODE) g_counts[i] = 0;
}

// ---------------- z_sq: bit-exact emulation of XLA GPU row reduction ----------------
// 256-wide f32 row reduce: 128 threads, vector_size=2,
// per-thread fl(x0^2 + x1^2), per-warp shfl_down tree (16,8,4,2,1),
// 4 warp partials combined as (w0+w2)+(w1+w3). All mul.rn/add.rn, no FMA.
__global__ void vq_zsq_kernel(const float* __restrict__ z) {
    __shared__ float wsum[4];
    const int n = blockIdx.x;
    const int t = threadIdx.x;              // 0..127
    const int b = n >> 10, nlow = n & 1023;
    const float* base = z + (size_t)b * 262144 + nlow;
    const float x0 = base[(size_t)(2 * t)     * 1024];
    const float x1 = base[(size_t)(2 * t + 1) * 1024];
    float v = __fadd_rn(__fmul_rn(x0, x0), __fmul_rn(x1, x1));
    #pragma unroll
    for (int off = 16; off > 0; off >>= 1)
        v = __fadd_rn(v, __shfl_down_sync(0xffffffffu, v, off));
    if ((t & 31) == 0) wsum[t >> 5] = v;
    __syncthreads();
    if (t == 0)
        g_zsq[n] = __fadd_rn(__fadd_rn(wsum[0], wsum[2]),
                             __fadd_rn(wsum[1], wsum[3]));
}

// ---------------- fused fp32 GEMM + quantized argmin ----------------
// Reference selection: argmin_j of fl(zsq_n - 2*m_nj)  (e_sq is swallowed by
// fp32 rounding at |zsq|~256), ties -> lowest j. m computed in plain fp32 with
// an ascending-k FFMA chain (bit-exact vs cublas SGEMM rank-1-update order).
__global__ __launch_bounds__(256, 2)
void vq_argmin_kernel(const float* __restrict__ z, const float* __restrict__ e_w) {
    __shared__ float sZ[TK][TM];       // [k][row]
    __shared__ float sE[TK][TN + 1];   // [k][col]
    __shared__ float sZq[TM];
    __shared__ float sVal[TM][16];
    __shared__ int   sIdx[TM][16];

    const int tid = threadIdx.x;
    const int tx = tid & 15;
    const int ty = tid >> 4;
    const int r0 = blockIdx.x * TM;    // 64 | 1024, never straddles a batch
    const int b  = r0 >> 10;
    const int nlow0 = r0 & 1023;
    const float* zbase = z + (size_t)b * 262144 + nlow0;

    if (tid < TM) sZq[tid] = g_zsq[r0 + tid];

    float bestV[4];
    int   bestI[4];
    #pragma unroll
    for (int r = 0; r < 4; r++) { bestV[r] = 3.402823e38f; bestI[r] = 0; }

    float myZsq[4];
    __syncthreads();
    #pragma unroll
    for (int r = 0; r < 4; r++) myZsq[r] = sZq[ty * 4 + r];

    for (int jt = 0; jt < N_CODE / TN; jt++) {
        float acc[4][8];
        #pragma unroll
        for (int r = 0; r < 4; r++)
            #pragma unroll
            for (int i = 0; i < 8; i++) acc[r][i] = 0.f;

        #pragma unroll 1
        for (int kt = 0; kt < E_DIM / TK; kt++) {
            const int k0 = kt * TK;
            {   // Z tile: 64 rows x 32 k (coalesced over rows)
                const int row = tid & 63;
                const int d0  = tid >> 6;          // 0..3
                #pragma unroll
                for (int u = 0; u < 8; u++) {
                    const int d = d0 + u * 4;
                    sZ[d][row] = zbase[(size_t)(k0 + d) * 1024 + row];
                }
            }
            {   // E tile: 128 codes x 32 k (coalesced over k)
                const int d  = tid & 31;
                const int jj = tid >> 5;           // 0..7
                const float* eb = e_w + (size_t)(jt * TN) * E_DIM + k0 + d;
                #pragma unroll
                for (int u = 0; u < 16; u++) {
                    const int j = jj + u * 8;
                    sE[d][j] = eb[(size_t)j * E_DIM];
                }
            }
            __syncthreads();
            #pragma unroll
            for (int k = 0; k < TK; k++) {         // ascending k: cublas-like chain
                const float4 av = *(const float4*)&sZ[k][ty * 4];
                float a[4] = {av.x, av.y, av.z, av.w};
                float bb[8];
                #pragma unroll
                for (int i = 0; i < 8; i++) bb[i] = sE[k][tx + 16 * i];
                #pragma unroll
                for (int r = 0; r < 4; r++)
                    #pragma unroll
                    for (int i = 0; i < 8; i++) acc[r][i] = fmaf(a[r], bb[i], acc[r][i]);
            }
            __syncthreads();
        }
        // fold: s = fl(zsq - 2m), strict < over ascending j keeps lowest-index tie
        #pragma unroll
        for (int i = 0; i < 8; i++) {
            const int j = jt * TN + tx + 16 * i;
            #pragma unroll
            for (int r = 0; r < 4; r++) {
                const float s = __fsub_rn(myZsq[r], __fmul_rn(2.0f, acc[r][i]));
                if (s < bestV[r]) { bestV[r] = s; bestI[r] = j; }
            }
        }
    }

    #pragma unroll
    for (int r = 0; r < 4; r++) {
        sVal[ty * 4 + r][tx] = bestV[r];
        sIdx[ty * 4 + r][tx] = bestI[r];
    }
    __syncthreads();
    if (tid < TM) {
        float bv = sVal[tid][0];
        int   bi = sIdx[tid][0];
        #pragma unroll
        for (int t = 1; t < 16; t++) {
            const float v  = sVal[tid][t];
            const int   ii = sIdx[tid][t];
            if (v < bv || (v == bv && ii < bi)) { bv = v; bi = ii; }
        }
        g_indices[r0 + tid] = bi;
    }
}

// ---------------- scatter: one_hot ones, indices-as-float, histogram ----------------
__global__ void vq_scatter_kernel(float* __restrict__ one_hot,
                                  float* __restrict__ out_idx,
                                  int write_onehot, int write_idx) {
    const int n = blockIdx.x * blockDim.x + threadIdx.x;
    if (n >= N_PTS) return;
    const int idx = g_indices[n];
    atomicAdd(&g_counts[idx], 1);
    if (write_onehot) one_hot[(size_t)n * N_CODE + idx] = 1.0f;
    if (write_idx)    out_idx[n] = (float)idx;
}

// ---------------- z_q_st + per-block loss partials ----------------
// z_q_st must be fl(z + fl(q - z)) — NOT q — to match reference rounding.
__global__ void vq_zq_kernel(const float* __restrict__ z,
                             const float* __restrict__ e_w,
                             float* __restrict__ out_zq, int write_zq) {
    __shared__ float sred[8];
    const int e = blockIdx.x * blockDim.x + threadIdx.x;   // 0 .. 4194303
    const int b    = e >> 18;
    const int rem  = e & 262143;
    const int c    = rem >> 10;
    const int nlow = rem & 1023;
    const int n    = (b << 10) + nlow;
    const float zv = z[e];
    const float q  = e_w[(size_t)g_indices[n] * E_DIM + c];
    const float d  = __fsub_rn(q, zv);
    if (write_zq) out_zq[e] = __fadd_rn(zv, d);
    float s = __fmul_rn(d, d);
    #pragma unroll
    for (int o = 16; o > 0; o >>= 1) s += __shfl_down_sync(0xffffffffu, s, o);
    const int lane = threadIdx.x & 31, wid = threadIdx.x >> 5;
    if (lane == 0) sred[wid] = s;
    __syncthreads();
    if (wid == 0) {
        float v = (lane < 8) ? sred[lane] : 0.f;
        #pragma unroll
        for (int o = 4; o > 0; o >>= 1) v += __shfl_down_sync(0xffffffffu, v, o);
        if (lane == 0) g_loss_part[blockIdx.x] = v;
    }
}

// ---------------- finalize: loss + perplexity ----------------
__global__ void vq_finalize_kernel(float* __restrict__ out,
                                   long long loss_off, long long ppl_off,
                                   int write_loss, int write_ppl) {
    __shared__ float sh[256];
    const int tid = threadIdx.x;

    float ls = 0.f;
    for (int i = tid; i < N_PTS; i += 256) ls += g_loss_part[i];
    sh[tid] = ls;
    __syncthreads();
    for (int o = 128; o > 0; o >>= 1) {
        if (tid < o) sh[tid] += sh[tid + o];
        __syncthreads();
    }
    const float loss_sum = sh[0];
    __syncthreads();

    float ps = 0.f;
    for (int j = tid; j < N_CODE; j += 256) {
        const float p = (float)g_counts[j] * (1.0f / (float)N_PTS);
        ps += p * logf(p + 1e-10f);
    }
    sh[tid] = ps;
    __syncthreads();
    for (int o = 128; o > 0; o >>= 1) {
        if (tid < o) sh[tid] += sh[tid + o];
        __syncthreads();
    }
    if (tid == 0) {
        if (write_loss) out[loss_off] = loss_sum * (1.25f / (float)Z_ELEMS);
        if (write_ppl)  out[ppl_off]  = expf(-sh[0]);
    }
}

// ---------------- launch ----------------
extern "C" void kernel_launch(void* const* d_in, const int* in_sizes, int n_in,
                              void* d_out, int out_size) {
    const float* z   = (const float*)d_in[0];
    const float* e_w = (const float*)d_in[1];
    float* out = (float*)d_out;

    // output layout: prefix of (loss[1], z_q_st[4194304], ppl[1], one_hot[134217728], indices[16384])
    const long long sizes[5] = {1, Z_ELEMS, 1, ONE_HOT_ELEMS, N_PTS};
    long long off[5];
    int present[5];
    long long cum = 0;
    for (int i = 0; i < 5; i++) {
        off[i] = cum;
        present[i] = (cum + sizes[i] <= (long long)out_size) ? 1 : 0;
        if (present[i]) cum += sizes[i];
    }

    vq_zero_kernel<<<(N_CODE + 255) / 256, 256>>>();
    vq_zsq_kernel<<<N_PTS, 128>>>(z);
    if (present[3])
        cudaMemsetAsync(out + off[3], 0, (size_t)ONE_HOT_ELEMS * sizeof(float));
    vq_argmin_kernel<<<N_PTS / TM, 256>>>(z, e_w);
    vq_scatter_kernel<<<(N_PTS + 255) / 256, 256>>>(
        present[3] ? out + off[3] : out,
        present[4] ? out + off[4] : out,
        present[3], present[4]);
    vq_zq_kernel<<<Z_ELEMS / 256, 256>>>(z, e_w,
        present[1] ? out + off[1] : out, present[1]);
    vq_finalize_kernel<<<1, 256>>>(out, off[0], off[2], present[0], present[2]);
}